// round 3
// baseline (speedup 1.0000x reference)
#include <cuda_runtime.h>
#include <cstdint>

#define D_DIM 4096
#define K_SEL 2048
#define NT    512
#define EPT   8
#define FULL  0xFFFFFFFFu
#define NB    24          // histogram bins over [-0.12, 0.12), width 0.01
#define BCAP  64          // per-bin capture capacity (12-sigma margin)
#define INV_W 100.0f
#define OFF_W 12.0f       // -LO/W
#define NEG_INF __int_as_float(0xff800000)

// warp 0 only: exact rank jrank (1-based from top) among m (<=64) values in buf
__device__ __forceinline__ void rank64(const float* buf, int m, int jrank,
                                       int lane, float* s_T) {
    float g0 = (lane      < m) ? buf[lane]      : NEG_INF;
    float g1 = (lane + 32 < m) ? buf[lane + 32] : NEG_INF;
    int gt0 = 0, eq0 = 0, gt1 = 0, eq1 = 0;
#pragma unroll
    for (int d = 0; d < 32; d++) {
        float o0 = __shfl_sync(FULL, g0, d);
        float o1 = __shfl_sync(FULL, g1, d);
        gt0 += (o0 > g0) + (o1 > g0);
        eq0 += (o0 == g0) + (o1 == g0);   // eq includes self
        gt1 += (o0 > g1) + (o1 > g1);
        eq1 += (o0 == g1) + (o1 == g1);
    }
    if (lane      < m && gt0 < jrank && gt0 + eq0 >= jrank) *s_T = g0;
    if (lane + 32 < m && gt1 < jrank && gt1 + eq1 >= jrank) *s_T = g1;
}

__global__ __launch_bounds__(NT, 4)
void topk_mask_kernel(const float* __restrict__ x, float* __restrict__ out) {
    __shared__ int   s_hist[NB];
    __shared__ float s_bbuf[NB * BCAP];   // per-bin captured values
    __shared__ int   s_chi;               // count of j >= NB (above range)
    __shared__ int   s_state;             // 1 = histogram path valid
    __shared__ int   s_b, s_chib, s_m;
    __shared__ float gbuf[BCAP];
    __shared__ float s_T;
    __shared__ int   s_c2[2];             // fallback counters (parity buffered)

    const int tid  = threadIdx.x;
    const int lane = tid & 31;
    const size_t row = blockIdx.x;

    const float4* xin  = reinterpret_cast<const float4*>(x   + row * (size_t)D_DIM);
    float4*       xout = reinterpret_cast<float4*>      (out + row * (size_t)D_DIM);

    if (tid < NB) s_hist[tid] = 0;
    if (tid == NB) { s_chi = 0; s_state = 0; s_m = 0; }

    float vals[EPT];
#pragma unroll
    for (int i = 0; i < 2; i++) {
        float4 v = __ldcs(xin + i * NT + tid);
        vals[4*i+0] = v.x; vals[4*i+1] = v.y;
        vals[4*i+2] = v.z; vals[4*i+3] = v.w;
    }
    __syncthreads();

    // ---- Round A: fused histogram count + in-bin value capture ----
    int chi = 0;
#pragma unroll
    for (int i = 0; i < EPT; i++) {
        float s = fmaf(vals[i], INV_W, OFF_W);   // monotone map
        int j = __float2int_rd(s);
        chi += (j >= NB);
        if ((unsigned)j < (unsigned)NB) {
            int pos = atomicAdd(&s_hist[j], 1);
            if (pos < BCAP) s_bbuf[j * BCAP + pos] = vals[i];
        }
    }
    chi = __reduce_add_sync(FULL, chi);
    if (lane == 0) atomicAdd(&s_chi, chi);
    __syncthreads();

    // ---- Warp 0: suffix-scan bins, select crossing bin ----
    if (tid < 32) {
        const int chitop = s_chi;
        const int hv = (lane < NB) ? s_hist[lane] : 0;
        int S = hv;
#pragma unroll
        for (int d = 1; d < 32; d <<= 1) {
            int o = __shfl_down_sync(FULL, S, d);
            S += (lane + d < 32) ? o : 0;
        }
        // S = count of elements in bins [lane..NB); cnt(>= edge_lane) = chitop + S
        bool p = (lane < NB) && (chitop + S >= K_SEL);
        unsigned mk = __ballot_sync(FULL, p);
        if (mk != 0 && chitop < K_SEL) {
            int b = 31 - __clz(mk);              // highest bin still >= K
            if (lane == b && hv <= BCAP) {
                s_b = b;
                s_chib = chitop + S - hv;        // count strictly above bin b
                s_m = hv;
                s_state = 1;
            }
        }
    }
    __syncthreads();

    if (s_state) {
        // ---- exact rank among captured bin values ----
        if (tid < 32)
            rank64(&s_bbuf[s_b * BCAP], s_m, K_SEL - s_chib, lane, &s_T);
        __syncthreads();
    } else {
        // ======== rare exact fallback (threshold outside range / overflow) ====
        float B = 0.24f;
        int CHIv = 0, CLOv = 0, ps = 0, ok = 0;
        for (int a = 0; a < 40 && !ok; a++) {
            // count >= B
            if (tid == 0) s_c2[ps & 1] = 0;
            __syncthreads();
            { int c = 0;
#pragma unroll
              for (int i = 0; i < EPT; i++) c += (vals[i] >= B);
              c = __reduce_add_sync(FULL, c);
              if (lane == 0) atomicAdd(&s_c2[ps & 1], c); }
            __syncthreads();
            CHIv = s_c2[ps & 1]; ps++;
            // count >= -B
            if (tid == 0) s_c2[ps & 1] = 0;
            __syncthreads();
            { int c = 0;
#pragma unroll
              for (int i = 0; i < EPT; i++) c += (vals[i] >= -B);
              c = __reduce_add_sync(FULL, c);
              if (lane == 0) atomicAdd(&s_c2[ps & 1], c); }
            __syncthreads();
            CLOv = s_c2[ps & 1]; ps++;
            ok = (CHIv < K_SEL && K_SEL <= CLOv);
            if (!ok) B *= 2.0f;
        }
        float lo = -B, hi = B;
        int clo = CLOv, chi2 = CHIv, deg = !ok, it = 0;
        while (!deg && clo - chi2 > BCAP) {
            if (it >= 24) { deg = 1; break; }
            float t = (float)(clo - K_SEL) / (float)(clo - chi2);
            t = fminf(fmaxf(t, 0.10f), 0.90f);
            float mid = lo + t * (hi - lo);
            if (mid <= lo || mid >= hi) { deg = 1; break; }
            if (tid == 0) s_c2[ps & 1] = 0;
            __syncthreads();
            { int c = 0;
#pragma unroll
              for (int i = 0; i < EPT; i++) c += (vals[i] >= mid);
              c = __reduce_add_sync(FULL, c);
              if (lane == 0) atomicAdd(&s_c2[ps & 1], c); }
            __syncthreads();
            int c = s_c2[ps & 1]; ps++;
            if (c >= K_SEL) { lo = mid; clo = c; }
            else            { hi = mid; chi2 = c; }
            it++;
        }
        if (deg) {
            if (tid == 0) s_T = lo;     // duplicate-collapse safety net
            __syncthreads();
        } else {
            if (tid == 0) s_m = 0;
            __syncthreads();
#pragma unroll
            for (int i = 0; i < EPT; i++) {
                float v = vals[i];
                if (v >= lo && v < hi) {
                    int p2 = atomicAdd(&s_m, 1);
                    if (p2 < BCAP) gbuf[p2] = v;
                }
            }
            __syncthreads();
            if (tid < 32)
                rank64(gbuf, s_m, K_SEL - chi2, lane, &s_T);
            __syncthreads();
        }
    }

    // ---- apply mask and stream out ----
    const float tf = s_T;
#pragma unroll
    for (int i = 0; i < 2; i++) {
        float4 w;
        w.x = (vals[4*i+0] >= tf) ? vals[4*i+0] : 0.0f;
        w.y = (vals[4*i+1] >= tf) ? vals[4*i+1] : 0.0f;
        w.z = (vals[4*i+2] >= tf) ? vals[4*i+2] : 0.0f;
        w.w = (vals[4*i+3] >= tf) ? vals[4*i+3] : 0.0f;
        __stcs(xout + i * NT + tid, w);
    }
}

extern "C" void kernel_launch(void* const* d_in, const int* in_sizes, int n_in,
                              void* d_out, int out_size) {
    const float* x = (const float*)d_in[0];
    float* out = (float*)d_out;
    int n = in_sizes[0];
    int rows = n / D_DIM;                 // 16384 for (4, 4096, 4096)
    topk_mask_kernel<<<rows, NT>>>(x, out);
}